// round 5
// baseline (speedup 1.0000x reference)
#include <cuda_runtime.h>
#include <cuda_fp16.h>

// AdditiveAttention: out[b,i,:] = softmax_j( sum_h tanh(qp+kp)*wv, mask j<vl ) @ values
// B=8, LQ=128, LK=1024, D=512, H=256, DV=512

static constexpr int B_  = 8;
static constexpr int LQ_ = 128;
static constexpr int LK_ = 1024;
static constexpr int D_  = 512;
static constexpr int H_  = 256;
static constexpr int H2_ = 128;
static constexpr int DV_ = 512;
static constexpr int QT  = 8;
static constexpr int NTH = 384;   // 12 warps: 4 producers + 8 consumers
static constexpr int TJ  = 256;   // key tile
static constexpr int EP  = 12;    // padded s_e row (bank-conflict relief)

__device__ __half  g_qh[B_ * LQ_ * H_];     // q proj [row][h] fp16
__device__ __half2 g_kT[B_ * H2_ * LK_];    // k proj transposed [b][h2][j]

// ---------------- helpers ----------------
__device__ __forceinline__ unsigned cvt_tf32(float f) {
    unsigned r;
    asm("cvt.rna.tf32.f32 %0, %1;" : "=r"(r) : "f"(f));
    return r;
}
__device__ __forceinline__ void mma_tf32(float* c, const unsigned* a, const unsigned* b) {
    asm volatile(
        "mma.sync.aligned.m16n8k8.row.col.f32.tf32.tf32.f32 "
        "{%0,%1,%2,%3}, {%4,%5,%6,%7}, {%8,%9}, {%0,%1,%2,%3};"
        : "+f"(c[0]), "+f"(c[1]), "+f"(c[2]), "+f"(c[3])
        : "r"(a[0]), "r"(a[1]), "r"(a[2]), "r"(a[3]), "r"(b[0]), "r"(b[1]));
}
__device__ __forceinline__ __half2 htanh2(__half2 x) {
    unsigned xi = *reinterpret_cast<unsigned*>(&x), yi;
    asm("tanh.approx.f16x2 %0, %1;" : "=r"(yi) : "r"(xi));
    return *reinterpret_cast<__half2*>(&yi);
}
__device__ __forceinline__ float warp_sum(float v) {
#pragma unroll
    for (int off = 16; off; off >>= 1) v += __shfl_xor_sync(0xffffffffu, v, off);
    return v;
}

// ---------------- fused projections: tf32 mma, tile 64x64, 128 threads ----------------
__global__ __launch_bounds__(128) void proj_mma(const float* __restrict__ Aq,
                                                const float* __restrict__ Ak,
                                                const float* __restrict__ Wq,
                                                const float* __restrict__ Wk) {
    __shared__ unsigned As[64][36];
    __shared__ unsigned Ws[32][72];

    const bool is_q = (blockIdx.y < 16);
    const float* A = is_q ? Aq : Ak;
    const float* W = is_q ? Wq : Wk;
    const int m0 = (is_q ? blockIdx.y : (blockIdx.y - 16)) * 64;
    const int n0 = blockIdx.x * 64;

    const int tid = threadIdx.x, warp = tid >> 5, lane = tid & 31;
    const int wm = (warp & 1) * 32, wn = (warp >> 1) * 32;
    const int g = lane >> 2, tg = lane & 3;

    float c[2][4][4];
#pragma unroll
    for (int mt = 0; mt < 2; mt++)
#pragma unroll
        for (int nt = 0; nt < 4; nt++)
#pragma unroll
            for (int i = 0; i < 4; i++) c[mt][nt][i] = 0.f;

    for (int k0 = 0; k0 < D_; k0 += 32) {
#pragma unroll
        for (int r = 0; r < 4; r++) {
            int row = (tid >> 3) + r * 16;
            float4 v = *(const float4*)&A[(size_t)(m0 + row) * D_ + k0 + (tid & 7) * 4];
            uint4 u = make_uint4(cvt_tf32(v.x), cvt_tf32(v.y), cvt_tf32(v.z), cvt_tf32(v.w));
            *(uint4*)&As[row][(tid & 7) * 4] = u;
        }
#pragma unroll
        for (int r = 0; r < 4; r++) {
            int row = (tid >> 4) + r * 8;
            float4 v = *(const float4*)&W[(size_t)(k0 + row) * H_ + n0 + (tid & 15) * 4];
            uint4 u = make_uint4(cvt_tf32(v.x), cvt_tf32(v.y), cvt_tf32(v.z), cvt_tf32(v.w));
            *(uint4*)&Ws[row][(tid & 15) * 4] = u;
        }
        __syncthreads();
#pragma unroll
        for (int ks = 0; ks < 4; ks++) {
            const int kb = ks * 8;
            unsigned a[2][4], b[4][2];
#pragma unroll
            for (int mt = 0; mt < 2; mt++) {
                int rb = wm + mt * 16 + g;
                a[mt][0] = As[rb][kb + tg];
                a[mt][1] = As[rb + 8][kb + tg];
                a[mt][2] = As[rb][kb + tg + 4];
                a[mt][3] = As[rb + 8][kb + tg + 4];
            }
#pragma unroll
            for (int nt = 0; nt < 4; nt++) {
                int cb = wn + nt * 8 + g;
                b[nt][0] = Ws[kb + tg][cb];
                b[nt][1] = Ws[kb + tg + 4][cb];
            }
#pragma unroll
            for (int mt = 0; mt < 2; mt++)
#pragma unroll
                for (int nt = 0; nt < 4; nt++) mma_tf32(c[mt][nt], a[mt], b[nt]);
        }
        __syncthreads();
    }

#pragma unroll
    for (int mt = 0; mt < 2; mt++)
#pragma unroll
        for (int nt = 0; nt < 4; nt++) {
            int row = m0 + wm + mt * 16 + g;
            int col = n0 + wn + nt * 8 + tg * 2;
            __half2 lo = __floats2half2_rn(c[mt][nt][0], c[mt][nt][1]);
            __half2 hi = __floats2half2_rn(c[mt][nt][2], c[mt][nt][3]);
            if (is_q) {
                *(__half2*)&g_qh[(size_t)row * H_ + col] = lo;
                *(__half2*)&g_qh[(size_t)(row + 8) * H_ + col] = hi;
            } else {
                int b_ = row >> 10, j = row & 1023;
                int h2 = col >> 1;
                g_kT[((size_t)b_ * H2_ + h2) * LK_ + j] = lo;
                g_kT[((size_t)b_ * H2_ + h2) * LK_ + (j + 8)] = hi;
            }
        }
}

// ---------------- fused attention: 4 producer + 8 consumer warps ----------------
__global__ __launch_bounds__(NTH, 1) void fused_attn(
    const float* __restrict__ values,
    const float* __restrict__ wv,
    const int* __restrict__ valid_lens,
    float* __restrict__ out) {
    __shared__ float   s_e[2][TJ][EP];   // exp(score) tiles, [j][q] (24 KB)
    __shared__ __half2 s_q[H2_][QT];     // q proj [h2][q] (4 KB)
    __shared__ __half2 s_w[H2_];         // wv pairs
    __shared__ float   s_psum[4][QT];

    const int b  = blockIdx.x >> 4;
    const int q0 = (blockIdx.x & 15) * QT;
    const int tid = threadIdx.x, warp = tid >> 5, lane = tid & 31;
    const int vl = valid_lens[b];
    const bool uniform = (vl == 0);
    const int T = uniform ? (LK_ / TJ) : ((vl + TJ - 1) / TJ);

    if (tid < H2_) s_w[tid] = __floats2half2_rn(wv[2 * tid], wv[2 * tid + 1]);
    for (int i = tid; i < H2_ * QT; i += NTH) {
        int h2 = i >> 3, q = i & 7;
        s_q[h2][q] = ((const __half2*)g_qh)[(size_t)(b * LQ_ + q0 + q) * H2_ + h2];
    }
    __syncthreads();

    if (warp < 4) {
        // ================= producers: lane owns 2 adjacent j =================
        const int jl2 = warp * 64 + lane * 2;           // 0..254 within tile
        const __half2* kb0 = g_kT + (size_t)b * H2_ * LK_;
        float sum8[QT];
#pragma unroll
        for (int q = 0; q < QT; q++) sum8[q] = 0.f;

        auto produce = [&](int t) {
            const int j = t * TJ + jl2;
            float e0[QT], e1[QT];
            if (uniform) {
#pragma unroll
                for (int q = 0; q < QT; q++) { e0[q] = 1.f; e1[q] = 1.f; }
            } else if (t * TJ + warp * 64 >= vl) {
                // whole warp masked
#pragma unroll
                for (int q = 0; q < QT; q++) { e0[q] = 0.f; e1[q] = 0.f; }
            } else {
                const __half2* kc = kb0 + j;
                float acc0[QT], acc1[QT];
#pragma unroll
                for (int q = 0; q < QT; q++) { acc0[q] = 0.f; acc1[q] = 0.f; }

                float2 kf[2][4];                         // double-buffered 4-h2 group
#pragma unroll
                for (int hh = 0; hh < 4; hh++)
                    kf[0][hh] = *(const float2*)(kc + (size_t)hh * LK_);

#pragma unroll 2
                for (int g4 = 0; g4 < 32; g4++) {
                    const int cur = g4 & 1;
                    if (g4 < 31) {
#pragma unroll
                        for (int hh = 0; hh < 4; hh++)
                            kf[cur ^ 1][hh] =
                                *(const float2*)(kc + (size_t)((g4 + 1) * 4 + hh) * LK_);
                    }
                    __half2 a0[QT], a1[QT];
#pragma unroll
                    for (int q = 0; q < QT; q++) {
                        a0[q] = __floats2half2_rn(0.f, 0.f);
                        a1[q] = __floats2half2_rn(0.f, 0.f);
                    }
#pragma unroll
                    for (int hh = 0; hh < 4; hh++) {
                        const int h2 = g4 * 4 + hh;
                        const __half2 k2a = ((const __half2*)&kf[cur][hh])[0];
                        const __half2 k2b = ((const __half2*)&kf[cur][hh])[1];
                        const __half2 w2 = s_w[h2];
                        const uint4 qa = *(const uint4*)&s_q[h2][0];
                        const uint4 qb = *(const uint4*)&s_q[h2][4];
                        const __half2* qv = (const __half2*)&qa;
                        const __half2* qw = (const __half2*)&qb;
#pragma unroll
                        for (int q = 0; q < 4; q++) {
                            a0[q] = __hfma2(htanh2(__hadd2(qv[q], k2a)), w2, a0[q]);
                            a1[q] = __hfma2(htanh2(__hadd2(qv[q], k2b)), w2, a1[q]);
                        }
#pragma unroll
                        for (int q = 0; q < 4; q++) {
                            a0[4 + q] = __hfma2(htanh2(__hadd2(qw[q], k2a)), w2, a0[4 + q]);
                            a1[4 + q] = __hfma2(htanh2(__hadd2(qw[q], k2b)), w2, a1[4 + q]);
                        }
                    }
#pragma unroll
                    for (int q = 0; q < QT; q++) {
                        float2 f0 = __half22float2(a0[q]);
                        float2 f1 = __half22float2(a1[q]);
                        acc0[q] += f0.x + f0.y;
                        acc1[q] += f1.x + f1.y;
                    }
                }
#pragma unroll
                for (int q = 0; q < QT; q++) {
                    e0[q] = (j < vl) ? __expf(acc0[q]) : 0.f;
                    e1[q] = (j + 1 < vl) ? __expf(acc1[q]) : 0.f;
                }
            }
#pragma unroll
            for (int q = 0; q < QT; q++) sum8[q] += e0[q] + e1[q];
            const int buf = t & 1;
            *(float4*)&s_e[buf][jl2][0] = make_float4(e0[0], e0[1], e0[2], e0[3]);
            *(float4*)&s_e[buf][jl2][4] = make_float4(e0[4], e0[5], e0[6], e0[7]);
            *(float4*)&s_e[buf][jl2 + 1][0] = make_float4(e1[0], e1[1], e1[2], e1[3]);
            *(float4*)&s_e[buf][jl2 + 1][4] = make_float4(e1[4], e1[5], e1[6], e1[7]);
        };

        produce(0);
        __syncthreads();
        for (int t = 0; t < T; t++) {
            if (t + 1 < T) {
                produce(t + 1);
            } else {
#pragma unroll
                for (int q = 0; q < QT; q++) {
                    float sq = warp_sum(sum8[q]);
                    if (lane == 0) s_psum[warp][q] = sq;
                }
            }
            __syncthreads();
        }
    } else {
        // ================= consumers =================
        const int c = (warp - 4) * 64 + lane * 2;       // warp owns 64 columns
        const float* vb = values + (size_t)b * LK_ * DV_;
        unsigned long long acc2[QT];
#pragma unroll
        for (int q = 0; q < QT; q++) acc2[q] = 0ull;

        __syncthreads();                                 // matches producers' post-produce(0)
        for (int t = 0; t < T; t++) {
            const int buf = t & 1;
            const float* vrow = vb + (size_t)t * TJ * DV_ + c;
#pragma unroll 8
            for (int jl = 0; jl < TJ; jl++) {
                const float4 elo = *(const float4*)&s_e[buf][jl][0];
                const float4 ehi = *(const float4*)&s_e[buf][jl][4];
                const unsigned long long v2 =
                    *(const unsigned long long*)(vrow + (size_t)jl * DV_);
                const float* ef0 = (const float*)&elo;
                const float* ef1 = (const float*)&ehi;
#pragma unroll
                for (int q = 0; q < 4; q++) {
                    unsigned long long a2;
                    asm("mov.b64 %0, {%1, %1};" : "=l"(a2) : "f"(ef0[q]));
                    asm("fma.rn.f32x2 %0, %1, %2, %0;" : "+l"(acc2[q]) : "l"(a2), "l"(v2));
                }
#pragma unroll
                for (int q = 0; q < 4; q++) {
                    unsigned long long a2;
                    asm("mov.b64 %0, {%1, %1};" : "=l"(a2) : "f"(ef1[q]));
                    asm("fma.rn.f32x2 %0, %1, %2, %0;" : "+l"(acc2[4 + q]) : "l"(a2), "l"(v2));
                }
            }
            __syncthreads();
        }

#pragma unroll
        for (int q = 0; q < QT; q++) {
            float sum = 0.f;
#pragma unroll
            for (int w = 0; w < 4; w++) sum += s_psum[w][q];
            const float inv = 1.f / sum;
            float lo, hi;
            asm("mov.b64 {%0, %1}, %2;" : "=f"(lo), "=f"(hi) : "l"(acc2[q]));
            *(float2*)&out[(size_t)(b * LQ_ + q0 + q) * DV_ + c] =
                make_float2(lo * inv, hi * inv);
        }
    }
}

extern "C" void kernel_launch(void* const* d_in, const int* in_sizes, int n_in,
                              void* d_out, int out_size) {
    const float* queries = (const float*)d_in[0];
    const float* keys    = (const float*)d_in[1];
    const float* values  = (const float*)d_in[2];
    const float* Wq      = (const float*)d_in[3];
    const float* Wk      = (const float*)d_in[4];
    const float* wv      = (const float*)d_in[5];
    const int*   vlen    = (const int*)d_in[6];
    float* out = (float*)d_out;

    proj_mma<<<dim3(H_ / 64, 16 + 128), 128>>>(queries, keys, Wq, Wk);
    fused_attn<<<B_ * (LQ_ / QT), NTH>>>(values, wv, vlen, out);
}

// round 6
// speedup vs baseline: 1.1496x; 1.1496x over previous
#include <cuda_runtime.h>
#include <cuda_fp16.h>

// AdditiveAttention: out[b,i,:] = softmax_j( sum_h tanh(qp+kp)*wv, mask j<vl ) @ values
// B=8, LQ=128, LK=1024, D=512, H=256, DV=512

static constexpr int B_  = 8;
static constexpr int LQ_ = 128;
static constexpr int LK_ = 1024;
static constexpr int D_  = 512;
static constexpr int H_  = 256;
static constexpr int H2_ = 128;
static constexpr int DV_ = 512;
static constexpr int QT  = 8;
static constexpr int SPL = 2;      // key splits
static constexpr int TJS = 512;    // keys per split
static constexpr int NTH = 256;    // 8 warps
static constexpr int EP  = 12;     // padded s_e row
static constexpr int NQT = B_ * (LQ_ / QT);   // 128 q-tiles

__device__ __half  g_qh[B_ * LQ_ * H_];      // q proj [row][h] fp16
__device__ __half2 g_kT[B_ * H2_ * LK_];     // k proj transposed [b][h2][j]
__device__ float   g_pAV[NQT][SPL][QT][DV_]; // partial e*V (16 MB)
__device__ float   g_psum[NQT][SPL][QT];     // partial sum(e)

// ---------------- helpers ----------------
__device__ __forceinline__ unsigned cvt_tf32(float f) {
    unsigned r;
    asm("cvt.rna.tf32.f32 %0, %1;" : "=r"(r) : "f"(f));
    return r;
}
__device__ __forceinline__ void mma_tf32(float* c, const unsigned* a, const unsigned* b) {
    asm volatile(
        "mma.sync.aligned.m16n8k8.row.col.f32.tf32.tf32.f32 "
        "{%0,%1,%2,%3}, {%4,%5,%6,%7}, {%8,%9}, {%0,%1,%2,%3};"
        : "+f"(c[0]), "+f"(c[1]), "+f"(c[2]), "+f"(c[3])
        : "r"(a[0]), "r"(a[1]), "r"(a[2]), "r"(a[3]), "r"(b[0]), "r"(b[1]));
}
__device__ __forceinline__ __half2 htanh2(__half2 x) {
    unsigned xi = *reinterpret_cast<unsigned*>(&x), yi;
    asm("tanh.approx.f16x2 %0, %1;" : "=r"(yi) : "r"(xi));
    return *reinterpret_cast<__half2*>(&yi);
}
__device__ __forceinline__ float warp_sum(float v) {
#pragma unroll
    for (int off = 16; off; off >>= 1) v += __shfl_xor_sync(0xffffffffu, v, off);
    return v;
}

// ---------------- fused projections: tf32 mma, tile 64x64, 128 threads ----------------
__global__ __launch_bounds__(128) void proj_mma(const float* __restrict__ Aq,
                                                const float* __restrict__ Ak,
                                                const float* __restrict__ Wq,
                                                const float* __restrict__ Wk) {
    __shared__ unsigned As[64][36];
    __shared__ unsigned Ws[32][72];

    const bool is_q = (blockIdx.y < 16);
    const float* A = is_q ? Aq : Ak;
    const float* W = is_q ? Wq : Wk;
    const int m0 = (is_q ? blockIdx.y : (blockIdx.y - 16)) * 64;
    const int n0 = blockIdx.x * 64;

    const int tid = threadIdx.x, warp = tid >> 5, lane = tid & 31;
    const int wm = (warp & 1) * 32, wn = (warp >> 1) * 32;
    const int g = lane >> 2, tg = lane & 3;

    float c[2][4][4];
#pragma unroll
    for (int mt = 0; mt < 2; mt++)
#pragma unroll
        for (int nt = 0; nt < 4; nt++)
#pragma unroll
            for (int i = 0; i < 4; i++) c[mt][nt][i] = 0.f;

    for (int k0 = 0; k0 < D_; k0 += 32) {
#pragma unroll
        for (int r = 0; r < 4; r++) {
            int row = (tid >> 3) + r * 16;
            float4 v = *(const float4*)&A[(size_t)(m0 + row) * D_ + k0 + (tid & 7) * 4];
            uint4 u = make_uint4(cvt_tf32(v.x), cvt_tf32(v.y), cvt_tf32(v.z), cvt_tf32(v.w));
            *(uint4*)&As[row][(tid & 7) * 4] = u;
        }
#pragma unroll
        for (int r = 0; r < 4; r++) {
            int row = (tid >> 4) + r * 8;
            float4 v = *(const float4*)&W[(size_t)(k0 + row) * H_ + n0 + (tid & 15) * 4];
            uint4 u = make_uint4(cvt_tf32(v.x), cvt_tf32(v.y), cvt_tf32(v.z), cvt_tf32(v.w));
            *(uint4*)&Ws[row][(tid & 15) * 4] = u;
        }
        __syncthreads();
#pragma unroll
        for (int ks = 0; ks < 4; ks++) {
            const int kb = ks * 8;
            unsigned a[2][4], b[4][2];
#pragma unroll
            for (int mt = 0; mt < 2; mt++) {
                int rb = wm + mt * 16 + g;
                a[mt][0] = As[rb][kb + tg];
                a[mt][1] = As[rb + 8][kb + tg];
                a[mt][2] = As[rb][kb + tg + 4];
                a[mt][3] = As[rb + 8][kb + tg + 4];
            }
#pragma unroll
            for (int nt = 0; nt < 4; nt++) {
                int cb = wn + nt * 8 + g;
                b[nt][0] = Ws[kb + tg][cb];
                b[nt][1] = Ws[kb + tg + 4][cb];
            }
#pragma unroll
            for (int mt = 0; mt < 2; mt++)
#pragma unroll
                for (int nt = 0; nt < 4; nt++) mma_tf32(c[mt][nt], a[mt], b[nt]);
        }
        __syncthreads();
    }

#pragma unroll
    for (int mt = 0; mt < 2; mt++)
#pragma unroll
        for (int nt = 0; nt < 4; nt++) {
            int row = m0 + wm + mt * 16 + g;
            int col = n0 + wn + nt * 8 + tg * 2;
            __half2 lo = __floats2half2_rn(c[mt][nt][0], c[mt][nt][1]);
            __half2 hi = __floats2half2_rn(c[mt][nt][2], c[mt][nt][3]);
            if (is_q) {
                *(__half2*)&g_qh[(size_t)row * H_ + col] = lo;
                *(__half2*)&g_qh[(size_t)(row + 8) * H_ + col] = hi;
            } else {
                int b_ = row >> 10, j = row & 1023;
                int h2 = col >> 1;
                g_kT[((size_t)b_ * H2_ + h2) * LK_ + j] = lo;
                g_kT[((size_t)b_ * H2_ + h2) * LK_ + (j + 8)] = hi;
            }
        }
}

// ---------------- split-K partial attention ----------------
// block = (qtile, split). All 8 warps: scores+exp -> smem, then partial AV -> scratch.
__global__ __launch_bounds__(NTH, 2) void partial_attn(
    const float* __restrict__ values,
    const float* __restrict__ wv,
    const int* __restrict__ valid_lens) {
    __shared__ float   s_e[TJS][EP];     // exp(score) [j][q] (24 KB)
    __shared__ __half2 s_q[H2_][QT];     // q proj [h2][q] (4 KB)
    __shared__ __half2 s_w[H2_];
    __shared__ float   s_psum[8][QT];

    const int qt = blockIdx.x >> 1;
    const int s  = blockIdx.x & 1;
    const int b  = qt >> 4;
    const int q0 = (qt & 15) * QT;
    const int tid = threadIdx.x, warp = tid >> 5, lane = tid & 31;
    const int vl = valid_lens[b];
    const bool uniform = (vl == 0);
    const int jb = s * TJS;
    int vll = uniform ? TJS : (vl - jb);          // local valid length
    vll = vll < 0 ? 0 : (vll > TJS ? TJS : vll);

    if (tid < H2_) s_w[tid] = __floats2half2_rn(wv[2 * tid], wv[2 * tid + 1]);
    for (int i = tid; i < H2_ * QT; i += NTH) {
        int h2 = i >> 3, q = i & 7;
        s_q[h2][q] = ((const __half2*)g_qh)[(size_t)(b * LQ_ + q0 + q) * H2_ + h2];
    }
    __syncthreads();

    // ---- Phase 1: scores -> exp, lane owns 2 adjacent local j ----
    {
        const int jl2 = warp * 64 + lane * 2;          // 0..510
        float e0[QT], e1[QT];
        if (uniform) {
#pragma unroll
            for (int q = 0; q < QT; q++) { e0[q] = 1.f; e1[q] = 1.f; }
        } else if (warp * 64 >= vll) {                 // whole warp masked
#pragma unroll
            for (int q = 0; q < QT; q++) { e0[q] = 0.f; e1[q] = 0.f; }
        } else {
            const __half2* kc = g_kT + (size_t)b * H2_ * LK_ + (jb + jl2);
            float acc0[QT], acc1[QT];
#pragma unroll
            for (int q = 0; q < QT; q++) { acc0[q] = 0.f; acc1[q] = 0.f; }

            float2 kf[2][4];
#pragma unroll
            for (int hh = 0; hh < 4; hh++)
                kf[0][hh] = *(const float2*)(kc + (size_t)hh * LK_);

#pragma unroll 2
            for (int g4 = 0; g4 < 32; g4++) {
                const int cur = g4 & 1;
                if (g4 < 31) {
#pragma unroll
                    for (int hh = 0; hh < 4; hh++)
                        kf[cur ^ 1][hh] =
                            *(const float2*)(kc + (size_t)((g4 + 1) * 4 + hh) * LK_);
                }
                __half2 a0[QT], a1[QT];
#pragma unroll
                for (int q = 0; q < QT; q++) {
                    a0[q] = __floats2half2_rn(0.f, 0.f);
                    a1[q] = __floats2half2_rn(0.f, 0.f);
                }
#pragma unroll
                for (int hh = 0; hh < 4; hh++) {
                    const int h2 = g4 * 4 + hh;
                    const __half2 k2a = ((const __half2*)&kf[cur][hh])[0];
                    const __half2 k2b = ((const __half2*)&kf[cur][hh])[1];
                    const __half2 w2 = s_w[h2];
                    const uint4 qa = *(const uint4*)&s_q[h2][0];
                    const uint4 qb = *(const uint4*)&s_q[h2][4];
                    const __half2* qv = (const __half2*)&qa;
                    const __half2* qw = (const __half2*)&qb;
#pragma unroll
                    for (int q = 0; q < 4; q++) {
                        a0[q] = __hfma2(htanh2(__hadd2(qv[q], k2a)), w2, a0[q]);
                        a1[q] = __hfma2(htanh2(__hadd2(qv[q], k2b)), w2, a1[q]);
                    }
#pragma unroll
                    for (int q = 0; q < 4; q++) {
                        a0[4 + q] = __hfma2(htanh2(__hadd2(qw[q], k2a)), w2, a0[4 + q]);
                        a1[4 + q] = __hfma2(htanh2(__hadd2(qw[q], k2b)), w2, a1[4 + q]);
                    }
                }
#pragma unroll
                for (int q = 0; q < QT; q++) {
                    float2 f0 = __half22float2(a0[q]);
                    float2 f1 = __half22float2(a1[q]);
                    acc0[q] += f0.x + f0.y;
                    acc1[q] += f1.x + f1.y;
                }
            }
#pragma unroll
            for (int q = 0; q < QT; q++) {
                e0[q] = (jl2 < vll) ? __expf(acc0[q]) : 0.f;
                e1[q] = (jl2 + 1 < vll) ? __expf(acc1[q]) : 0.f;
            }
        }
        float sum8[QT];
#pragma unroll
        for (int q = 0; q < QT; q++) sum8[q] = e0[q] + e1[q];
        *(float4*)&s_e[jl2][0] = make_float4(e0[0], e0[1], e0[2], e0[3]);
        *(float4*)&s_e[jl2][4] = make_float4(e0[4], e0[5], e0[6], e0[7]);
        *(float4*)&s_e[jl2 + 1][0] = make_float4(e1[0], e1[1], e1[2], e1[3]);
        *(float4*)&s_e[jl2 + 1][4] = make_float4(e1[4], e1[5], e1[6], e1[7]);
#pragma unroll
        for (int q = 0; q < QT; q++) {
            float sq = warp_sum(sum8[q]);
            if (lane == 0) s_psum[warp][q] = sq;
        }
    }
    __syncthreads();

    // ---- Phase 2: partial sums to scratch ----
    if (warp == 0 && lane < QT) {
        float t = 0.f;
#pragma unroll
        for (int w = 0; w < 8; w++) t += s_psum[w][lane];
        g_psum[qt][s][lane] = t;
    }

    // ---- Phase 3: partial AV over this split's keys ----
    {
        const int c = warp * 64 + lane * 2;            // warp owns 64 columns
        const float* vb = values + (size_t)b * LK_ * DV_ + (size_t)jb * DV_ + c;
        unsigned long long acc2[QT];
#pragma unroll
        for (int q = 0; q < QT; q++) acc2[q] = 0ull;

        const int jlim = uniform ? TJS : ((vll + 3) & ~3);
#pragma unroll 8
        for (int jl = 0; jl < jlim; jl++) {
            const float4 elo = *(const float4*)&s_e[jl][0];
            const float4 ehi = *(const float4*)&s_e[jl][4];
            const unsigned long long v2 =
                *(const unsigned long long*)(vb + (size_t)jl * DV_);
            const float* ef0 = (const float*)&elo;
            const float* ef1 = (const float*)&ehi;
#pragma unroll
            for (int q = 0; q < 4; q++) {
                unsigned long long a2;
                asm("mov.b64 %0, {%1, %1};" : "=l"(a2) : "f"(ef0[q]));
                asm("fma.rn.f32x2 %0, %1, %2, %0;" : "+l"(acc2[q]) : "l"(a2), "l"(v2));
            }
#pragma unroll
            for (int q = 0; q < 4; q++) {
                unsigned long long a2;
                asm("mov.b64 %0, {%1, %1};" : "=l"(a2) : "f"(ef1[q]));
                asm("fma.rn.f32x2 %0, %1, %2, %0;" : "+l"(acc2[4 + q]) : "l"(a2), "l"(v2));
            }
        }
#pragma unroll
        for (int q = 0; q < QT; q++) {
            float lo, hi;
            asm("mov.b64 {%0, %1}, %2;" : "=f"(lo), "=f"(hi) : "l"(acc2[q]));
            *(float2*)&g_pAV[qt][s][q][c] = make_float2(lo, hi);
        }
    }
}

// ---------------- reduce: out = sum_s pAV / sum_s psum ----------------
__global__ __launch_bounds__(NTH) void reduce_attn(float* __restrict__ out) {
    __shared__ float s_inv[QT];
    const int qt = blockIdx.x;
    const int b = qt >> 4, q0 = (qt & 15) * QT;
    const int tid = threadIdx.x;

    if (tid < QT) {
        float t = g_psum[qt][0][tid] + g_psum[qt][1][tid];
        s_inv[tid] = 1.f / t;
    }
    __syncthreads();

    const int c = tid * 2;                            // 256 threads x 2 cols = 512
#pragma unroll
    for (int q = 0; q < QT; q++) {
        float2 a0 = *(const float2*)&g_pAV[qt][0][q][c];
        float2 a1 = *(const float2*)&g_pAV[qt][1][q][c];
        const float inv = s_inv[q];
        *(float2*)&out[(size_t)(b * LQ_ + q0 + q) * DV_ + c] =
            make_float2((a0.x + a1.x) * inv, (a0.y + a1.y) * inv);
    }
}

extern "C" void kernel_launch(void* const* d_in, const int* in_sizes, int n_in,
                              void* d_out, int out_size) {
    const float* queries = (const float*)d_in[0];
    const float* keys    = (const float*)d_in[1];
    const float* values  = (const float*)d_in[2];
    const float* Wq      = (const float*)d_in[3];
    const float* Wk      = (const float*)d_in[4];
    const float* wv      = (const float*)d_in[5];
    const int*   vlen    = (const int*)d_in[6];
    float* out = (float*)d_out;

    proj_mma<<<dim3(H_ / 64, 16 + 128), 128>>>(queries, keys, Wq, Wk);
    partial_attn<<<NQT * SPL, NTH>>>(values, wv, vlen);
    reduce_attn<<<NQT, NTH>>>(out);
}

// round 7
// speedup vs baseline: 1.7267x; 1.5020x over previous
#include <cuda_runtime.h>
#include <cuda_fp16.h>

// AdditiveAttention: out[b,i,:] = softmax_j( sum_h tanh(qp+kp)*wv, mask j<vl ) @ values
// B=8, LQ=128, LK=1024, D=512, H=256, DV=512

static constexpr int B_  = 8;
static constexpr int LQ_ = 128;
static constexpr int LK_ = 1024;
static constexpr int D_  = 512;
static constexpr int H_  = 256;
static constexpr int H2_ = 128;
static constexpr int DV_ = 512;
static constexpr int QT  = 8;
static constexpr int SPL = 4;      // key splits
static constexpr int TJS = 256;    // keys per split
static constexpr int NTH = 256;    // 8 warps
static constexpr int EP  = 12;     // padded s_e row
static constexpr int NQT = B_ * (LQ_ / QT);   // 128 q-tiles

__device__ __half  g_qh[B_ * LQ_ * H_];      // q proj [row][h] fp16
__device__ __half2 g_kT[B_ * H2_ * LK_];     // k proj transposed [b][h2][j]
__device__ float   g_pAV[NQT][SPL][QT][DV_]; // partial e*V (8 MB)
__device__ float   g_psum[NQT][SPL][QT];     // partial sum(e)

// ---------------- helpers ----------------
__device__ __forceinline__ void ldsm_x4(unsigned* r, const void* p) {
    unsigned addr = (unsigned)__cvta_generic_to_shared(p);
    asm volatile("ldmatrix.sync.aligned.m8n8.x4.shared.b16 {%0,%1,%2,%3}, [%4];"
                 : "=r"(r[0]), "=r"(r[1]), "=r"(r[2]), "=r"(r[3]) : "r"(addr));
}
__device__ __forceinline__ void ldsm_x4_t(unsigned* r, const void* p) {
    unsigned addr = (unsigned)__cvta_generic_to_shared(p);
    asm volatile("ldmatrix.sync.aligned.m8n8.x4.trans.shared.b16 {%0,%1,%2,%3}, [%4];"
                 : "=r"(r[0]), "=r"(r[1]), "=r"(r[2]), "=r"(r[3]) : "r"(addr));
}
__device__ __forceinline__ void mma_f16(float* c, const unsigned* a, const unsigned* b) {
    asm volatile(
        "mma.sync.aligned.m16n8k16.row.col.f32.f16.f16.f32 "
        "{%0,%1,%2,%3}, {%4,%5,%6,%7}, {%8,%9}, {%0,%1,%2,%3};"
        : "+f"(c[0]), "+f"(c[1]), "+f"(c[2]), "+f"(c[3])
        : "r"(a[0]), "r"(a[1]), "r"(a[2]), "r"(a[3]), "r"(b[0]), "r"(b[1]));
}
__device__ __forceinline__ __half2 htanh2(__half2 x) {
    unsigned xi = *reinterpret_cast<unsigned*>(&x), yi;
    asm("tanh.approx.f16x2 %0, %1;" : "=r"(yi) : "r"(xi));
    return *reinterpret_cast<__half2*>(&yi);
}
__device__ __forceinline__ float warp_sum(float v) {
#pragma unroll
    for (int off = 16; off; off >>= 1) v += __shfl_xor_sync(0xffffffffu, v, off);
    return v;
}

// ---------------- projections: fp16 mma + ldmatrix, tile 64x64, 128 threads ----------------
// blockIdx.y < 16 -> queries @ Wq -> g_qh; else keys @ Wk -> g_kT (transposed)
__global__ __launch_bounds__(128) void proj_mma(const float* __restrict__ Aq,
                                                const float* __restrict__ Ak,
                                                const float* __restrict__ Wq,
                                                const float* __restrict__ Wk) {
    __shared__ __half As[64][40];   // stride 40 halves = 80B: conflict-free ldmatrix
    __shared__ __half Ws[32][72];   // stride 72 halves = 144B

    const bool is_q = (blockIdx.y < 16);
    const float* A = is_q ? Aq : Ak;
    const float* W = is_q ? Wq : Wk;
    const int m0 = (is_q ? blockIdx.y : (blockIdx.y - 16)) * 64;
    const int n0 = blockIdx.x * 64;

    const int tid = threadIdx.x, warp = tid >> 5, lane = tid & 31;
    const int wm = (warp & 1) * 32, wn = (warp >> 1) * 32;
    const int g = lane >> 2, tg = lane & 3;

    float c[2][4][4];
#pragma unroll
    for (int mt = 0; mt < 2; mt++)
#pragma unroll
        for (int nt = 0; nt < 4; nt++)
#pragma unroll
            for (int i = 0; i < 4; i++) c[mt][nt][i] = 0.f;

    for (int k0 = 0; k0 < D_; k0 += 32) {
#pragma unroll
        for (int r = 0; r < 4; r++) {
            int row = (tid >> 3) + r * 16, col = (tid & 7) * 4;
            float4 v = *(const float4*)&A[(size_t)(m0 + row) * D_ + k0 + col];
            *(__half2*)&As[row][col]     = __floats2half2_rn(v.x, v.y);
            *(__half2*)&As[row][col + 2] = __floats2half2_rn(v.z, v.w);
        }
#pragma unroll
        for (int r = 0; r < 4; r++) {
            int row = (tid >> 4) + r * 8, col = (tid & 15) * 4;
            float4 v = *(const float4*)&W[(size_t)(k0 + row) * H_ + n0 + col];
            *(__half2*)&Ws[row][col]     = __floats2half2_rn(v.x, v.y);
            *(__half2*)&Ws[row][col + 2] = __floats2half2_rn(v.z, v.w);
        }
        __syncthreads();
#pragma unroll
        for (int ks = 0; ks < 2; ks++) {
            unsigned a[2][4], bf[2][4];
#pragma unroll
            for (int mt = 0; mt < 2; mt++)
                ldsm_x4(a[mt], &As[wm + mt * 16 + (lane & 15)][ks * 16 + ((lane >> 4) << 3)]);
#pragma unroll
            for (int np = 0; np < 2; np++)
                ldsm_x4_t(bf[np], &Ws[ks * 16 + (lane & 15)][wn + np * 16 + ((lane >> 4) << 3)]);
#pragma unroll
            for (int mt = 0; mt < 2; mt++)
#pragma unroll
                for (int np = 0; np < 2; np++) {
                    mma_f16(c[mt][np * 2],     a[mt], &bf[np][0]);
                    mma_f16(c[mt][np * 2 + 1], a[mt], &bf[np][2]);
                }
        }
        __syncthreads();
    }

#pragma unroll
    for (int mt = 0; mt < 2; mt++)
#pragma unroll
        for (int nt = 0; nt < 4; nt++) {
            int row = m0 + wm + mt * 16 + g;
            int col = n0 + wn + nt * 8 + tg * 2;
            __half2 lo = __floats2half2_rn(c[mt][nt][0], c[mt][nt][1]);
            __half2 hi = __floats2half2_rn(c[mt][nt][2], c[mt][nt][3]);
            if (is_q) {
                *(__half2*)&g_qh[(size_t)row * H_ + col] = lo;
                *(__half2*)&g_qh[(size_t)(row + 8) * H_ + col] = hi;
            } else {
                int b_ = row >> 10, j = row & 1023;
                int h2 = col >> 1;
                g_kT[((size_t)b_ * H2_ + h2) * LK_ + j] = lo;
                g_kT[((size_t)b_ * H2_ + h2) * LK_ + (j + 8)] = hi;
            }
        }
}

// ---------------- split-K partial attention: block = (qtile, split) ----------------
__global__ __launch_bounds__(NTH, 2) void partial_attn(
    const float* __restrict__ values,
    const float* __restrict__ wv,
    const int* __restrict__ valid_lens) {
    __shared__ float   s_e[TJS][EP];     // exp(score) [j][q] (12 KB)
    __shared__ __half2 s_q[H2_][QT];     // q proj [h2][q] (4 KB)
    __shared__ __half2 s_w[H2_];
    __shared__ float   s_psum[8][QT];

    const int qt = blockIdx.x >> 2;
    const int s  = blockIdx.x & 3;
    const int b  = qt >> 4;
    const int q0 = (qt & 15) * QT;
    const int tid = threadIdx.x, warp = tid >> 5, lane = tid & 31;
    const int vl = valid_lens[b];
    const bool uniform = (vl == 0);
    const int jb = s * TJS;
    int vll = uniform ? TJS : (vl - jb);
    vll = vll < 0 ? 0 : (vll > TJS ? TJS : vll);

    if (!uniform && vll == 0) {           // fully-masked split: zero scratch, exit
        if (tid < QT) g_psum[qt][s][tid] = 0.f;
        for (int i = tid; i < QT * (DV_ / 4); i += NTH)
            ((float4*)&g_pAV[qt][s][0][0])[i] = make_float4(0.f, 0.f, 0.f, 0.f);
        return;
    }

    if (tid < H2_) s_w[tid] = __floats2half2_rn(wv[2 * tid], wv[2 * tid + 1]);
    for (int i = tid; i < H2_ * QT; i += NTH) {
        int h2 = i >> 3, q = i & 7;
        s_q[h2][q] = ((const __half2*)g_qh)[(size_t)(b * LQ_ + q0 + q) * H2_ + h2];
    }
    __syncthreads();

    // ---- Phase 1: lane owns 1 local j ----
    {
        const int jl = warp * 32 + lane;               // 0..255
        float e[QT];
        if (uniform) {
#pragma unroll
            for (int q = 0; q < QT; q++) e[q] = 1.f;
        } else if (warp * 32 >= vll) {                 // whole warp masked
#pragma unroll
            for (int q = 0; q < QT; q++) e[q] = 0.f;
        } else {
            const __half2* kc = g_kT + (size_t)b * H2_ * LK_ + (jb + jl);
            float acc[QT];
#pragma unroll
            for (int q = 0; q < QT; q++) acc[q] = 0.f;

            __half2 kf[2][4];
#pragma unroll
            for (int hh = 0; hh < 4; hh++) kf[0][hh] = kc[(size_t)hh * LK_];

#pragma unroll 2
            for (int g4 = 0; g4 < 32; g4++) {
                const int cur = g4 & 1;
                if (g4 < 31) {
#pragma unroll
                    for (int hh = 0; hh < 4; hh++)
                        kf[cur ^ 1][hh] = kc[(size_t)((g4 + 1) * 4 + hh) * LK_];
                }
                __half2 ah[QT];
#pragma unroll
                for (int q = 0; q < QT; q++) ah[q] = __floats2half2_rn(0.f, 0.f);
#pragma unroll
                for (int hh = 0; hh < 4; hh++) {
                    const int h2 = g4 * 4 + hh;
                    const __half2 k2 = kf[cur][hh];
                    const __half2 w2 = s_w[h2];
                    const uint4 qa = *(const uint4*)&s_q[h2][0];
                    const uint4 qb = *(const uint4*)&s_q[h2][4];
                    const __half2* qv = (const __half2*)&qa;
                    const __half2* qw = (const __half2*)&qb;
#pragma unroll
                    for (int q = 0; q < 4; q++)
                        ah[q] = __hfma2(htanh2(__hadd2(qv[q], k2)), w2, ah[q]);
#pragma unroll
                    for (int q = 0; q < 4; q++)
                        ah[4 + q] = __hfma2(htanh2(__hadd2(qw[q], k2)), w2, ah[4 + q]);
                }
#pragma unroll
                for (int q = 0; q < QT; q++) {
                    float2 f = __half22float2(ah[q]);
                    acc[q] += f.x + f.y;
                }
            }
#pragma unroll
            for (int q = 0; q < QT; q++)
                e[q] = (jl < vll) ? __expf(acc[q]) : 0.f;
        }
        *(float4*)&s_e[jl][0] = make_float4(e[0], e[1], e[2], e[3]);
        *(float4*)&s_e[jl][4] = make_float4(e[4], e[5], e[6], e[7]);
        float sum8[QT];
#pragma unroll
        for (int q = 0; q < QT; q++) sum8[q] = e[q];
#pragma unroll
        for (int q = 0; q < QT; q++) {
            float sq = warp_sum(sum8[q]);
            if (lane == 0) s_psum[warp][q] = sq;
        }
    }
    __syncthreads();

    if (warp == 0 && lane < QT) {
        float t = 0.f;
#pragma unroll
        for (int w = 0; w < 8; w++) t += s_psum[w][lane];
        g_psum[qt][s][lane] = t;
    }

    // ---- Phase 3: partial AV, q-pair packed f32x2 FMA ----
    {
        const int c = warp * 64 + lane * 2;            // warp owns 64 columns
        const float* vb = values + (size_t)b * LK_ * DV_ + (size_t)jb * DV_ + c;
        unsigned long long acc2[4][2];                 // [qpair][colx]
#pragma unroll
        for (int p = 0; p < 4; p++) { acc2[p][0] = 0ull; acc2[p][1] = 0ull; }

        const int jlim = uniform ? TJS : vll;
#pragma unroll 8
        for (int j = 0; j < jlim; j++) {
            const ulonglong2 ea = *(const ulonglong2*)&s_e[j][0];  // (q0,q1),(q2,q3)
            const ulonglong2 eb = *(const ulonglong2*)&s_e[j][4];  // (q4,q5),(q6,q7)
            const float2 v = *(const float2*)(vb + (size_t)j * DV_);
            unsigned long long vx, vy;
            asm("mov.b64 %0, {%1, %1};" : "=l"(vx) : "f"(v.x));
            asm("mov.b64 %0, {%1, %1};" : "=l"(vy) : "f"(v.y));
            asm("fma.rn.f32x2 %0, %1, %2, %0;" : "+l"(acc2[0][0]) : "l"(ea.x), "l"(vx));
            asm("fma.rn.f32x2 %0, %1, %2, %0;" : "+l"(acc2[0][1]) : "l"(ea.x), "l"(vy));
            asm("fma.rn.f32x2 %0, %1, %2, %0;" : "+l"(acc2[1][0]) : "l"(ea.y), "l"(vx));
            asm("fma.rn.f32x2 %0, %1, %2, %0;" : "+l"(acc2[1][1]) : "l"(ea.y), "l"(vy));
            asm("fma.rn.f32x2 %0, %1, %2, %0;" : "+l"(acc2[2][0]) : "l"(eb.x), "l"(vx));
            asm("fma.rn.f32x2 %0, %1, %2, %0;" : "+l"(acc2[2][1]) : "l"(eb.x), "l"(vy));
            asm("fma.rn.f32x2 %0, %1, %2, %0;" : "+l"(acc2[3][0]) : "l"(eb.y), "l"(vx));
            asm("fma.rn.f32x2 %0, %1, %2, %0;" : "+l"(acc2[3][1]) : "l"(eb.y), "l"(vy));
        }
#pragma unroll
        for (int p = 0; p < 4; p++) {
            float l0, h0, l1, h1;
            asm("mov.b64 {%0, %1}, %2;" : "=f"(l0), "=f"(h0) : "l"(acc2[p][0]));
            asm("mov.b64 {%0, %1}, %2;" : "=f"(l1), "=f"(h1) : "l"(acc2[p][1]));
            *(float2*)&g_pAV[qt][s][2 * p][c]     = make_float2(l0, l1);
            *(float2*)&g_pAV[qt][s][2 * p + 1][c] = make_float2(h0, h1);
        }
    }
}

// ---------------- reduce: out = sum_s pAV / sum_s psum ----------------
__global__ __launch_bounds__(NTH) void reduce_attn(float* __restrict__ out) {
    __shared__ float s_inv[QT];
    const int qt = blockIdx.x;
    const int b = qt >> 4, q0 = (qt & 15) * QT;
    const int tid = threadIdx.x;

    if (tid < QT) {
        float t = 0.f;
#pragma unroll
        for (int s = 0; s < SPL; s++) t += g_psum[qt][s][tid];
        s_inv[tid] = 1.f / t;
    }
    __syncthreads();

    const int c = tid * 2;
#pragma unroll
    for (int q = 0; q < QT; q++) {
        float2 a = make_float2(0.f, 0.f);
#pragma unroll
        for (int s = 0; s < SPL; s++) {
            float2 p = *(const float2*)&g_pAV[qt][s][q][c];
            a.x += p.x; a.y += p.y;
        }
        const float inv = s_inv[q];
        *(float2*)&out[(size_t)(b * LQ_ + q0 + q) * DV_ + c] =
            make_float2(a.x * inv, a.y * inv);
    }
}

extern "C" void kernel_launch(void* const* d_in, const int* in_sizes, int n_in,
                              void* d_out, int out_size) {
    const float* queries = (const float*)d_in[0];
    const float* keys    = (const float*)d_in[1];
    const float* values  = (const float*)d_in[2];
    const float* Wq      = (const float*)d_in[3];
    const float* Wk      = (const float*)d_in[4];
    const float* wv      = (const float*)d_in[5];
    const int*   vlen    = (const int*)d_in[6];
    float* out = (float*)d_out;

    proj_mma<<<dim3(H_ / 64, 16 + 128), 128>>>(queries, keys, Wq, Wk);
    partial_attn<<<NQT * SPL, NTH>>>(values, wv, vlen);
    reduce_attn<<<NQT, NTH>>>(out);
}

// round 8
// speedup vs baseline: 1.7553x; 1.0166x over previous
#include <cuda_runtime.h>
#include <cuda_fp16.h>

// AdditiveAttention: out[b,i,:] = softmax_j( sum_h tanh(qp+kp)*wv, mask j<vl ) @ values
// B=8, LQ=128, LK=1024, D=512, H=256, DV=512

static constexpr int B_  = 8;
static constexpr int LQ_ = 128;
static constexpr int LK_ = 1024;
static constexpr int D_  = 512;
static constexpr int H_  = 256;
static constexpr int H2_ = 128;
static constexpr int DV_ = 512;
static constexpr int QT  = 8;
static constexpr int SPL = 4;      // key splits
static constexpr int TJS = 256;    // keys per split
static constexpr int NTH = 256;    // 8 warps
static constexpr int EP  = 12;     // padded s_e row
static constexpr int NQT = B_ * (LQ_ / QT);   // 128 q-tiles
static constexpr int AROWS = B_ * LQ_ + B_ * LK_;  // 9216 combined A rows (q then k)

__device__ __half  g_Ah[AROWS * D_];         // fp16 copy of [queries; keys]
__device__ __half  g_Whq[D_ * H_];           // fp16 Wq
__device__ __half  g_Whk[D_ * H_];           // fp16 Wk
__device__ __half  g_qh[B_ * LQ_ * H_];      // q proj [row][h] fp16
__device__ __half2 g_kT[B_ * H2_ * LK_];     // k proj transposed [b][h2][j]
__device__ float   g_pAV[NQT][SPL][QT][DV_]; // partial e*V (8 MB)
__device__ float   g_psum[NQT][SPL][QT];     // partial sum(e)

// ---------------- helpers ----------------
__device__ __forceinline__ void cp16(void* dst, const void* src) {
    unsigned d = (unsigned)__cvta_generic_to_shared(dst);
    asm volatile("cp.async.cg.shared.global [%0], [%1], 16;" :: "r"(d), "l"(src));
}
__device__ __forceinline__ void ldsm_x4(unsigned* r, const void* p) {
    unsigned addr = (unsigned)__cvta_generic_to_shared(p);
    asm volatile("ldmatrix.sync.aligned.m8n8.x4.shared.b16 {%0,%1,%2,%3}, [%4];"
                 : "=r"(r[0]), "=r"(r[1]), "=r"(r[2]), "=r"(r[3]) : "r"(addr));
}
__device__ __forceinline__ void ldsm_x4_t(unsigned* r, const void* p) {
    unsigned addr = (unsigned)__cvta_generic_to_shared(p);
    asm volatile("ldmatrix.sync.aligned.m8n8.x4.trans.shared.b16 {%0,%1,%2,%3}, [%4];"
                 : "=r"(r[0]), "=r"(r[1]), "=r"(r[2]), "=r"(r[3]) : "r"(addr));
}
__device__ __forceinline__ void mma_f16(float* c, const unsigned* a, const unsigned* b) {
    asm volatile(
        "mma.sync.aligned.m16n8k16.row.col.f32.f16.f16.f32 "
        "{%0,%1,%2,%3}, {%4,%5,%6,%7}, {%8,%9}, {%0,%1,%2,%3};"
        : "+f"(c[0]), "+f"(c[1]), "+f"(c[2]), "+f"(c[3])
        : "r"(a[0]), "r"(a[1]), "r"(a[2]), "r"(a[3]), "r"(b[0]), "r"(b[1]));
}
__device__ __forceinline__ __half2 htanh2(__half2 x) {
    unsigned xi = *reinterpret_cast<unsigned*>(&x), yi;
    asm("tanh.approx.f16x2 %0, %1;" : "=r"(yi) : "r"(xi));
    return *reinterpret_cast<__half2*>(&yi);
}
__device__ __forceinline__ float warp_sum(float v) {
#pragma unroll
    for (int off = 16; off; off >>= 1) v += __shfl_xor_sync(0xffffffffu, v, off);
    return v;
}

// ---------------- convert inputs to fp16 ----------------
static constexpr int NQ4 = B_ * LQ_ * D_ / 4;
static constexpr int NK4 = B_ * LK_ * D_ / 4;
static constexpr int NW4 = D_ * H_ / 4;
static constexpr int TOT4 = NQ4 + NK4 + 2 * NW4;

__global__ __launch_bounds__(256) void to_half(const float* __restrict__ q,
                                               const float* __restrict__ k,
                                               const float* __restrict__ wq,
                                               const float* __restrict__ wk) {
    for (int i = blockIdx.x * 256 + threadIdx.x; i < TOT4; i += gridDim.x * 256) {
        const float4* src; __half* dst; int off;
        if (i < NQ4)                   { src = (const float4*)q;  dst = g_Ah;                off = i; }
        else if (i < NQ4 + NK4)        { src = (const float4*)k;  dst = g_Ah + (size_t)B_ * LQ_ * D_; off = i - NQ4; }
        else if (i < NQ4 + NK4 + NW4)  { src = (const float4*)wq; dst = g_Whq;              off = i - NQ4 - NK4; }
        else                           { src = (const float4*)wk; dst = g_Whk;              off = i - NQ4 - NK4 - NW4; }
        float4 v = src[off];
        *(__half2*)&dst[(size_t)off * 4]     = __floats2half2_rn(v.x, v.y);
        *(__half2*)&dst[(size_t)off * 4 + 2] = __floats2half2_rn(v.z, v.w);
    }
}

// ---------------- projections: fp16 mma + ldmatrix + cp.async pipeline ----------------
// blockIdx.y < 16 -> queries @ Wq -> g_qh; else keys @ Wk -> g_kT (transposed)
__global__ __launch_bounds__(128) void proj_mma() {
    __shared__ __half As[2][64][40];   // 80B rows (16B-multiple): cp.async + ldmatrix ok
    __shared__ __half Ws[2][32][72];   // 144B rows

    const bool is_q = (blockIdx.y < 16);
    const int m0 = (is_q ? blockIdx.y : (blockIdx.y - 16)) * 64;
    const int n0 = blockIdx.x * 64;
    const __half* Asrc = g_Ah + (size_t)((is_q ? 0 : B_ * LQ_) + m0) * D_;
    const __half* Wsrc = is_q ? g_Whq : g_Whk;

    const int tid = threadIdx.x, warp = tid >> 5, lane = tid & 31;
    const int wm = (warp & 1) * 32, wn = (warp >> 1) * 32;
    const int g = lane >> 2, tg = lane & 3;

    float c[2][4][4];
#pragma unroll
    for (int mt = 0; mt < 2; mt++)
#pragma unroll
        for (int nt = 0; nt < 4; nt++)
#pragma unroll
            for (int i = 0; i < 4; i++) c[mt][nt][i] = 0.f;

    auto load_stage = [&](int buf, int k0) {
#pragma unroll
        for (int cc = tid; cc < 256; cc += 128) {          // A: 64 rows x 32 halves
            int row = cc >> 2, col8 = (cc & 3) * 8;
            cp16(&As[buf][row][col8], Asrc + (size_t)row * D_ + k0 + col8);
        }
#pragma unroll
        for (int cc = tid; cc < 256; cc += 128) {          // W: 32 rows x 64 halves
            int row = cc >> 3, col8 = (cc & 7) * 8;
            cp16(&Ws[buf][row][col8], Wsrc + (size_t)(k0 + row) * H_ + n0 + col8);
        }
        asm volatile("cp.async.commit_group;" ::: "memory");
    };

    load_stage(0, 0);
    for (int t = 0; t < 16; t++) {
        if (t + 1 < 16) {
            load_stage((t + 1) & 1, (t + 1) * 32);
            asm volatile("cp.async.wait_group 1;" ::: "memory");
        } else {
            asm volatile("cp.async.wait_group 0;" ::: "memory");
        }
        __syncthreads();
        const int buf = t & 1;
#pragma unroll
        for (int ks = 0; ks < 2; ks++) {
            unsigned a[2][4], bf[2][4];
#pragma unroll
            for (int mt = 0; mt < 2; mt++)
                ldsm_x4(a[mt], &As[buf][wm + mt * 16 + (lane & 15)][ks * 16 + ((lane >> 4) << 3)]);
#pragma unroll
            for (int np = 0; np < 2; np++)
                ldsm_x4_t(bf[np], &Ws[buf][ks * 16 + (lane & 15)][wn + np * 16 + ((lane >> 4) << 3)]);
#pragma unroll
            for (int mt = 0; mt < 2; mt++)
#pragma unroll
                for (int np = 0; np < 2; np++) {
                    mma_f16(c[mt][np * 2],     a[mt], &bf[np][0]);
                    mma_f16(c[mt][np * 2 + 1], a[mt], &bf[np][2]);
                }
        }
        __syncthreads();
    }

#pragma unroll
    for (int mt = 0; mt < 2; mt++)
#pragma unroll
        for (int nt = 0; nt < 4; nt++) {
            int row = m0 + wm + mt * 16 + g;
            int col = n0 + wn + nt * 8 + tg * 2;
            __half2 lo = __floats2half2_rn(c[mt][nt][0], c[mt][nt][1]);
            __half2 hi = __floats2half2_rn(c[mt][nt][2], c[mt][nt][3]);
            if (is_q) {
                *(__half2*)&g_qh[(size_t)row * H_ + col] = lo;
                *(__half2*)&g_qh[(size_t)(row + 8) * H_ + col] = hi;
            } else {
                int b_ = row >> 10, j = row & 1023;
                int h2 = col >> 1;
                g_kT[((size_t)b_ * H2_ + h2) * LK_ + j] = lo;
                g_kT[((size_t)b_ * H2_ + h2) * LK_ + (j + 8)] = hi;
            }
        }
}

// ---------------- split-K partial attention: block = (qtile, split) ----------------
__global__ __launch_bounds__(NTH, 2) void partial_attn(
    const float* __restrict__ values,
    const float* __restrict__ wv,
    const int* __restrict__ valid_lens) {
    __shared__ float   s_e[TJS][EP];     // exp(score) [j][q] (12 KB)
    __shared__ __half2 s_q[H2_][QT];     // q proj [h2][q] (4 KB)
    __shared__ __half2 s_w[H2_];
    __shared__ float   s_psum[8][QT];

    const int qt = blockIdx.x >> 2;
    const int s  = blockIdx.x & 3;
    const int b  = qt >> 4;
    const int q0 = (qt & 15) * QT;
    const int tid = threadIdx.x, warp = tid >> 5, lane = tid & 31;
    const int vl = valid_lens[b];
    const bool uniform = (vl == 0);
    const int jb = s * TJS;
    int vll = uniform ? TJS : (vl - jb);
    vll = vll < 0 ? 0 : (vll > TJS ? TJS : vll);

    if (!uniform && vll == 0) {           // fully-masked split: zero scratch, exit
        if (tid < QT) g_psum[qt][s][tid] = 0.f;
        for (int i = tid; i < QT * (DV_ / 4); i += NTH)
            ((float4*)&g_pAV[qt][s][0][0])[i] = make_float4(0.f, 0.f, 0.f, 0.f);
        return;
    }

    if (tid < H2_) s_w[tid] = __floats2half2_rn(wv[2 * tid], wv[2 * tid + 1]);
    for (int i = tid; i < H2_ * QT; i += NTH) {
        int h2 = i >> 3, q = i & 7;
        s_q[h2][q] = ((const __half2*)g_qh)[(size_t)(b * LQ_ + q0 + q) * H2_ + h2];
    }
    __syncthreads();

    // ---- Phase 1: lane owns 1 local j ----
    {
        const int jl = warp * 32 + lane;               // 0..255
        float e[QT];
        if (uniform) {
#pragma unroll
            for (int q = 0; q < QT; q++) e[q] = 1.f;
        } else if (warp * 32 >= vll) {                 // whole warp masked
#pragma unroll
            for (int q = 0; q < QT; q++) e[q] = 0.f;
        } else {
            const __half2* kc = g_kT + (size_t)b * H2_ * LK_ + (jb + jl);
            float acc[QT];
#pragma unroll
            for (int q = 0; q < QT; q++) acc[q] = 0.f;

            __half2 kf[2][4];
#pragma unroll
            for (int hh = 0; hh < 4; hh++) kf[0][hh] = kc[(size_t)hh * LK_];

#pragma unroll 2
            for (int g4 = 0; g4 < 32; g4++) {
                const int cur = g4 & 1;
                if (g4 < 31) {
#pragma unroll
                    for (int hh = 0; hh < 4; hh++)
                        kf[cur ^ 1][hh] = kc[(size_t)((g4 + 1) * 4 + hh) * LK_];
                }
                __half2 ah[QT];
#pragma unroll
                for (int q = 0; q < QT; q++) ah[q] = __floats2half2_rn(0.f, 0.f);
#pragma unroll
                for (int hh = 0; hh < 4; hh++) {
                    const int h2 = g4 * 4 + hh;
                    const __half2 k2 = kf[cur][hh];
                    const __half2 w2 = s_w[h2];
                    const uint4 qa = *(const uint4*)&s_q[h2][0];
                    const uint4 qb = *(const uint4*)&s_q[h2][4];
                    const __half2* qv = (const __half2*)&qa;
                    const __half2* qw = (const __half2*)&qb;
#pragma unroll
                    for (int q = 0; q < 4; q++)
                        ah[q] = __hfma2(htanh2(__hadd2(qv[q], k2)), w2, ah[q]);
#pragma unroll
                    for (int q = 0; q < 4; q++)
                        ah[4 + q] = __hfma2(htanh2(__hadd2(qw[q], k2)), w2, ah[4 + q]);
                }
#pragma unroll
                for (int q = 0; q < QT; q++) {
                    float2 f = __half22float2(ah[q]);
                    acc[q] += f.x + f.y;
                }
            }
#pragma unroll
            for (int q = 0; q < QT; q++)
                e[q] = (jl < vll) ? __expf(acc[q]) : 0.f;
        }
        *(float4*)&s_e[jl][0] = make_float4(e[0], e[1], e[2], e[3]);
        *(float4*)&s_e[jl][4] = make_float4(e[4], e[5], e[6], e[7]);
        float sum8[QT];
#pragma unroll
        for (int q = 0; q < QT; q++) sum8[q] = e[q];
#pragma unroll
        for (int q = 0; q < QT; q++) {
            float sq = warp_sum(sum8[q]);
            if (lane == 0) s_psum[warp][q] = sq;
        }
    }
    __syncthreads();

    if (warp == 0 && lane < QT) {
        float t = 0.f;
#pragma unroll
        for (int w = 0; w < 8; w++) t += s_psum[w][lane];
        g_psum[qt][s][lane] = t;
    }

    // ---- Phase 3: partial AV, q-pair packed f32x2 FMA ----
    {
        const int c = warp * 64 + lane * 2;            // warp owns 64 columns
        const float* vb = values + (size_t)b * LK_ * DV_ + (size_t)jb * DV_ + c;
        unsigned long long acc2[4][2];                 // [qpair][colx]
#pragma unroll
        for (int p = 0; p < 4; p++) { acc2[p][0] = 0ull; acc2[p][1] = 0ull; }

        const int jlim = uniform ? TJS : vll;
#pragma unroll 8
        for (int j = 0; j < jlim; j++) {
            const ulonglong2 ea = *(const ulonglong2*)&s_e[j][0];  // (q0,q1),(q2,q3)
            const ulonglong2 eb = *(const ulonglong2*)&s_e[j][4];  // (q4,q5),(q6,q7)
            const float2 v = *(const float2*)(vb + (size_t)j * DV_);
            unsigned long long vx, vy;
            asm("mov.b64 %0, {%1, %1};" : "=l"(vx) : "f"(v.x));
            asm("mov.b64 %0, {%1, %1};" : "=l"(vy) : "f"(v.y));
            asm("fma.rn.f32x2 %0, %1, %2, %0;" : "+l"(acc2[0][0]) : "l"(ea.x), "l"(vx));
            asm("fma.rn.f32x2 %0, %1, %2, %0;" : "+l"(acc2[0][1]) : "l"(ea.x), "l"(vy));
            asm("fma.rn.f32x2 %0, %1, %2, %0;" : "+l"(acc2[1][0]) : "l"(ea.y), "l"(vx));
            asm("fma.rn.f32x2 %0, %1, %2, %0;" : "+l"(acc2[1][1]) : "l"(ea.y), "l"(vy));
            asm("fma.rn.f32x2 %0, %1, %2, %0;" : "+l"(acc2[2][0]) : "l"(eb.x), "l"(vx));
            asm("fma.rn.f32x2 %0, %1, %2, %0;" : "+l"(acc2[2][1]) : "l"(eb.x), "l"(vy));
            asm("fma.rn.f32x2 %0, %1, %2, %0;" : "+l"(acc2[3][0]) : "l"(eb.y), "l"(vx));
            asm("fma.rn.f32x2 %0, %1, %2, %0;" : "+l"(acc2[3][1]) : "l"(eb.y), "l"(vy));
        }
#pragma unroll
        for (int p = 0; p < 4; p++) {
            float l0, h0, l1, h1;
            asm("mov.b64 {%0, %1}, %2;" : "=f"(l0), "=f"(h0) : "l"(acc2[p][0]));
            asm("mov.b64 {%0, %1}, %2;" : "=f"(l1), "=f"(h1) : "l"(acc2[p][1]));
            *(float2*)&g_pAV[qt][s][2 * p][c]     = make_float2(l0, l1);
            *(float2*)&g_pAV[qt][s][2 * p + 1][c] = make_float2(h0, h1);
        }
    }
}

// ---------------- reduce: out = sum_s pAV / sum_s psum ----------------
__global__ __launch_bounds__(NTH) void reduce_attn(float* __restrict__ out) {
    __shared__ float s_inv[QT];
    const int qt = blockIdx.x;
    const int b = qt >> 4, q0 = (qt & 15) * QT;
    const int tid = threadIdx.x;

    if (tid < QT) {
        float t = 0.f;
#pragma unroll
        for (int s = 0; s < SPL; s++) t += g_psum[qt][s][tid];
        s_inv[tid] = 1.f / t;
    }
    __syncthreads();

    const int c = tid * 2;
#pragma unroll
    for (int q = 0; q < QT; q++) {
        float2 a = make_float2(0.f, 0.f);
#pragma unroll
        for (int s = 0; s < SPL; s++) {
            float2 p = *(const float2*)&g_pAV[qt][s][q][c];
            a.x += p.x; a.y += p.y;
        }
        const float inv = s_inv[q];
        *(float2*)&out[(size_t)(b * LQ_ + q0 + q) * DV_ + c] =
            make_float2(a.x * inv, a.y * inv);
    }
}

extern "C" void kernel_launch(void* const* d_in, const int* in_sizes, int n_in,
                              void* d_out, int out_size) {
    const float* queries = (const float*)d_in[0];
    const float* keys    = (const float*)d_in[1];
    const float* values  = (const float*)d_in[2];
    const float* Wq      = (const float*)d_in[3];
    const float* Wk      = (const float*)d_in[4];
    const float* wv      = (const float*)d_in[5];
    const int*   vlen    = (const int*)d_in[6];
    float* out = (float*)d_out;

    to_half<<<1024, 256>>>(queries, keys, Wq, Wk);
    proj_mma<<<dim3(H_ / 64, 16 + 128), 128>>>();
    partial_attn<<<NQT * SPL, NTH>>>(values, wv, vlen);
    reduce_attn<<<NQT, NTH>>>(out);
}

// round 9
// speedup vs baseline: 1.7674x; 1.0069x over previous
#include <cuda_runtime.h>
#include <cuda_fp16.h>

// AdditiveAttention: out[b,i,:] = softmax_j( sum_h tanh(qp+kp)*wv, mask j<vl ) @ values
// B=8, LQ=128, LK=1024, D=512, H=256, DV=512

static constexpr int B_  = 8;
static constexpr int LQ_ = 128;
static constexpr int LK_ = 1024;
static constexpr int D_  = 512;
static constexpr int H_  = 256;
static constexpr int H2_ = 128;
static constexpr int DV_ = 512;
static constexpr int QT  = 8;
static constexpr int SPL = 4;      // key splits
static constexpr int TJS = 256;    // keys per split
static constexpr int NTH = 256;    // 8 warps
static constexpr int EP  = 12;     // padded s_e row
static constexpr int NQT = B_ * (LQ_ / QT);   // 128 q-tiles
static constexpr int AROWS = B_ * LQ_ + B_ * LK_;  // 9216 combined A rows (q then k)

__device__ __half  g_Ah[AROWS * D_];         // fp16 copy of [queries; keys]
__device__ __half  g_Whq[D_ * H_];           // fp16 Wq
__device__ __half  g_Whk[D_ * H_];           // fp16 Wk
__device__ __half  g_qh[B_ * LQ_ * H_];      // q proj [row][h] fp16
__device__ __half2 g_kT[B_ * H2_ * LK_];     // k proj transposed [b][h2][j]
__device__ float   g_pAV[NQT][SPL][QT][DV_]; // partial e*V (8 MB)
__device__ float   g_psum[NQT][SPL][QT];     // partial sum(e)
__device__ unsigned g_tick[NQT];             // split completion tickets

// ---------------- helpers ----------------
__device__ __forceinline__ void cp16(void* dst, const void* src) {
    unsigned d = (unsigned)__cvta_generic_to_shared(dst);
    asm volatile("cp.async.cg.shared.global [%0], [%1], 16;" :: "r"(d), "l"(src));
}
__device__ __forceinline__ void ldsm_x4(unsigned* r, const void* p) {
    unsigned addr = (unsigned)__cvta_generic_to_shared(p);
    asm volatile("ldmatrix.sync.aligned.m8n8.x4.shared.b16 {%0,%1,%2,%3}, [%4];"
                 : "=r"(r[0]), "=r"(r[1]), "=r"(r[2]), "=r"(r[3]) : "r"(addr));
}
__device__ __forceinline__ void ldsm_x4_t(unsigned* r, const void* p) {
    unsigned addr = (unsigned)__cvta_generic_to_shared(p);
    asm volatile("ldmatrix.sync.aligned.m8n8.x4.trans.shared.b16 {%0,%1,%2,%3}, [%4];"
                 : "=r"(r[0]), "=r"(r[1]), "=r"(r[2]), "=r"(r[3]) : "r"(addr));
}
__device__ __forceinline__ void mma_f16(float* c, const unsigned* a, const unsigned* b) {
    asm volatile(
        "mma.sync.aligned.m16n8k16.row.col.f32.f16.f16.f32 "
        "{%0,%1,%2,%3}, {%4,%5,%6,%7}, {%8,%9}, {%0,%1,%2,%3};"
        : "+f"(c[0]), "+f"(c[1]), "+f"(c[2]), "+f"(c[3])
        : "r"(a[0]), "r"(a[1]), "r"(a[2]), "r"(a[3]), "r"(b[0]), "r"(b[1]));
}
__device__ __forceinline__ __half2 htanh2(__half2 x) {
    unsigned xi = *reinterpret_cast<unsigned*>(&x), yi;
    asm("tanh.approx.f16x2 %0, %1;" : "=r"(yi) : "r"(xi));
    return *reinterpret_cast<__half2*>(&yi);
}
__device__ __forceinline__ float warp_sum(float v) {
#pragma unroll
    for (int off = 16; off; off >>= 1) v += __shfl_xor_sync(0xffffffffu, v, off);
    return v;
}

// ---------------- convert inputs to fp16 (+ reset tickets) ----------------
static constexpr int NQ4 = B_ * LQ_ * D_ / 4;
static constexpr int NK4 = B_ * LK_ * D_ / 4;
static constexpr int NW4 = D_ * H_ / 4;
static constexpr int TOT4 = NQ4 + NK4 + 2 * NW4;

__global__ __launch_bounds__(256) void to_half(const float* __restrict__ q,
                                               const float* __restrict__ k,
                                               const float* __restrict__ wq,
                                               const float* __restrict__ wk) {
    if (blockIdx.x == 0 && threadIdx.x < NQT) g_tick[threadIdx.x] = 0u;
    for (int i = blockIdx.x * 256 + threadIdx.x; i < TOT4; i += gridDim.x * 256) {
        const float4* src; __half* dst; int off;
        if (i < NQ4)                   { src = (const float4*)q;  dst = g_Ah;                off = i; }
        else if (i < NQ4 + NK4)        { src = (const float4*)k;  dst = g_Ah + (size_t)B_ * LQ_ * D_; off = i - NQ4; }
        else if (i < NQ4 + NK4 + NW4)  { src = (const float4*)wq; dst = g_Whq;              off = i - NQ4 - NK4; }
        else                           { src = (const float4*)wk; dst = g_Whk;              off = i - NQ4 - NK4 - NW4; }
        float4 v = src[off];
        *(__half2*)&dst[(size_t)off * 4]     = __floats2half2_rn(v.x, v.y);
        *(__half2*)&dst[(size_t)off * 4 + 2] = __floats2half2_rn(v.z, v.w);
    }
}

// ---------------- projections: fp16 mma + ldmatrix + cp.async pipeline ----------------
__global__ __launch_bounds__(128) void proj_mma() {
    __shared__ __half As[2][64][40];
    __shared__ __half Ws[2][32][72];

    const bool is_q = (blockIdx.y < 16);
    const int m0 = (is_q ? blockIdx.y : (blockIdx.y - 16)) * 64;
    const int n0 = blockIdx.x * 64;
    const __half* Asrc = g_Ah + (size_t)((is_q ? 0 : B_ * LQ_) + m0) * D_;
    const __half* Wsrc = is_q ? g_Whq : g_Whk;

    const int tid = threadIdx.x, warp = tid >> 5, lane = tid & 31;
    const int wm = (warp & 1) * 32, wn = (warp >> 1) * 32;
    const int g = lane >> 2, tg = lane & 3;

    float c[2][4][4];
#pragma unroll
    for (int mt = 0; mt < 2; mt++)
#pragma unroll
        for (int nt = 0; nt < 4; nt++)
#pragma unroll
            for (int i = 0; i < 4; i++) c[mt][nt][i] = 0.f;

    auto load_stage = [&](int buf, int k0) {
#pragma unroll
        for (int cc = tid; cc < 256; cc += 128) {
            int row = cc >> 2, col8 = (cc & 3) * 8;
            cp16(&As[buf][row][col8], Asrc + (size_t)row * D_ + k0 + col8);
        }
#pragma unroll
        for (int cc = tid; cc < 256; cc += 128) {
            int row = cc >> 3, col8 = (cc & 7) * 8;
            cp16(&Ws[buf][row][col8], Wsrc + (size_t)(k0 + row) * H_ + n0 + col8);
        }
        asm volatile("cp.async.commit_group;" ::: "memory");
    };

    load_stage(0, 0);
    for (int t = 0; t < 16; t++) {
        if (t + 1 < 16) {
            load_stage((t + 1) & 1, (t + 1) * 32);
            asm volatile("cp.async.wait_group 1;" ::: "memory");
        } else {
            asm volatile("cp.async.wait_group 0;" ::: "memory");
        }
        __syncthreads();
        const int buf = t & 1;
#pragma unroll
        for (int ks = 0; ks < 2; ks++) {
            unsigned a[2][4], bf[2][4];
#pragma unroll
            for (int mt = 0; mt < 2; mt++)
                ldsm_x4(a[mt], &As[buf][wm + mt * 16 + (lane & 15)][ks * 16 + ((lane >> 4) << 3)]);
#pragma unroll
            for (int np = 0; np < 2; np++)
                ldsm_x4_t(bf[np], &Ws[buf][ks * 16 + (lane & 15)][wn + np * 16 + ((lane >> 4) << 3)]);
#pragma unroll
            for (int mt = 0; mt < 2; mt++)
#pragma unroll
                for (int np = 0; np < 2; np++) {
                    mma_f16(c[mt][np * 2],     a[mt], &bf[np][0]);
                    mma_f16(c[mt][np * 2 + 1], a[mt], &bf[np][2]);
                }
        }
        __syncthreads();
    }

#pragma unroll
    for (int mt = 0; mt < 2; mt++)
#pragma unroll
        for (int nt = 0; nt < 4; nt++) {
            int row = m0 + wm + mt * 16 + g;
            int col = n0 + wn + nt * 8 + tg * 2;
            __half2 lo = __floats2half2_rn(c[mt][nt][0], c[mt][nt][1]);
            __half2 hi = __floats2half2_rn(c[mt][nt][2], c[mt][nt][3]);
            if (is_q) {
                *(__half2*)&g_qh[(size_t)row * H_ + col] = lo;
                *(__half2*)&g_qh[(size_t)(row + 8) * H_ + col] = hi;
            } else {
                int b_ = row >> 10, j = row & 1023;
                int h2 = col >> 1;
                g_kT[((size_t)b_ * H2_ + h2) * LK_ + j] = lo;
                g_kT[((size_t)b_ * H2_ + h2) * LK_ + (j + 8)] = hi;
            }
        }
}

// ---------------- split-K partial attention + fused last-CTA reduce ----------------
__global__ __launch_bounds__(NTH, 2) void partial_attn(
    const float* __restrict__ values,
    const float* __restrict__ wv,
    const int* __restrict__ valid_lens,
    float* __restrict__ out) {
    __shared__ float   s_e[TJS][EP];
    __shared__ __half2 s_q[H2_][QT];
    __shared__ __half2 s_w[H2_];
    __shared__ float   s_psum[8][QT];
    __shared__ float   s_inv[QT];
    __shared__ int     s_last;

    const int qt = blockIdx.x >> 2;
    const int s  = blockIdx.x & 3;
    const int b  = qt >> 4;
    const int q0 = (qt & 15) * QT;
    const int tid = threadIdx.x, warp = tid >> 5, lane = tid & 31;
    const int vl = valid_lens[b];
    const bool uniform = (vl == 0);
    const int jb = s * TJS;
    int vll = uniform ? TJS : (vl - jb);
    vll = vll < 0 ? 0 : (vll > TJS ? TJS : vll);

    if (vll > 0) {       // active split: compute scores + partial AV
        if (tid < H2_) s_w[tid] = __floats2half2_rn(wv[2 * tid], wv[2 * tid + 1]);
        for (int i = tid; i < H2_ * QT; i += NTH) {
            int h2 = i >> 3, q = i & 7;
            s_q[h2][q] = ((const __half2*)g_qh)[(size_t)(b * LQ_ + q0 + q) * H2_ + h2];
        }
        __syncthreads();

        // ---- Phase 1: lane owns 1 local j ----
        {
            const int jl = warp * 32 + lane;
            float e[QT];
            if (uniform) {
#pragma unroll
                for (int q = 0; q < QT; q++) e[q] = 1.f;
            } else if (warp * 32 >= vll) {
#pragma unroll
                for (int q = 0; q < QT; q++) e[q] = 0.f;
            } else {
                const __half2* kc = g_kT + (size_t)b * H2_ * LK_ + (jb + jl);
                float acc[QT];
#pragma unroll
                for (int q = 0; q < QT; q++) acc[q] = 0.f;

                __half2 kf[2][4];
#pragma unroll
                for (int hh = 0; hh < 4; hh++) kf[0][hh] = kc[(size_t)hh * LK_];

#pragma unroll 2
                for (int g4 = 0; g4 < 32; g4++) {
                    const int cur = g4 & 1;
                    if (g4 < 31) {
#pragma unroll
                        for (int hh = 0; hh < 4; hh++)
                            kf[cur ^ 1][hh] = kc[(size_t)((g4 + 1) * 4 + hh) * LK_];
                    }
                    __half2 ah[QT];
#pragma unroll
                    for (int q = 0; q < QT; q++) ah[q] = __floats2half2_rn(0.f, 0.f);
#pragma unroll
                    for (int hh = 0; hh < 4; hh++) {
                        const int h2 = g4 * 4 + hh;
                        const __half2 k2 = kf[cur][hh];
                        const __half2 w2 = s_w[h2];
                        const uint4 qa = *(const uint4*)&s_q[h2][0];
                        const uint4 qb = *(const uint4*)&s_q[h2][4];
                        const __half2* qv = (const __half2*)&qa;
                        const __half2* qw = (const __half2*)&qb;
#pragma unroll
                        for (int q = 0; q < 4; q++)
                            ah[q] = __hfma2(htanh2(__hadd2(qv[q], k2)), w2, ah[q]);
#pragma unroll
                        for (int q = 0; q < 4; q++)
                            ah[4 + q] = __hfma2(htanh2(__hadd2(qw[q], k2)), w2, ah[4 + q]);
                    }
#pragma unroll
                    for (int q = 0; q < QT; q++) {
                        float2 f = __half22float2(ah[q]);
                        acc[q] += f.x + f.y;
                    }
                }
#pragma unroll
                for (int q = 0; q < QT; q++)
                    e[q] = (jl < vll) ? __expf(acc[q]) : 0.f;
            }
            *(float4*)&s_e[jl][0] = make_float4(e[0], e[1], e[2], e[3]);
            *(float4*)&s_e[jl][4] = make_float4(e[4], e[5], e[6], e[7]);
#pragma unroll
            for (int q = 0; q < QT; q++) {
                float sq = warp_sum(e[q]);
                if (lane == 0) s_psum[warp][q] = sq;
            }
        }
        __syncthreads();

        if (warp == 0 && lane < QT) {
            float t = 0.f;
#pragma unroll
            for (int w = 0; w < 8; w++) t += s_psum[w][lane];
            g_psum[qt][s][lane] = t;
        }

        // ---- Phase 3: partial AV, q-pair packed f32x2 FMA ----
        {
            const int c = warp * 64 + lane * 2;
            const float* vb = values + (size_t)b * LK_ * DV_ + (size_t)jb * DV_ + c;
            unsigned long long acc2[4][2];
#pragma unroll
            for (int p = 0; p < 4; p++) { acc2[p][0] = 0ull; acc2[p][1] = 0ull; }

            const int jlim = uniform ? TJS : vll;
#pragma unroll 8
            for (int j = 0; j < jlim; j++) {
                const ulonglong2 ea = *(const ulonglong2*)&s_e[j][0];
                const ulonglong2 eb = *(const ulonglong2*)&s_e[j][4];
                const float2 v = *(const float2*)(vb + (size_t)j * DV_);
                unsigned long long vx, vy;
                asm("mov.b64 %0, {%1, %1};" : "=l"(vx) : "f"(v.x));
                asm("mov.b64 %0, {%1, %1};" : "=l"(vy) : "f"(v.y));
                asm("fma.rn.f32x2 %0, %1, %2, %0;" : "+l"(acc2[0][0]) : "l"(ea.x), "l"(vx));
                asm("fma.rn.f32x2 %0, %1, %2, %0;" : "+l"(acc2[0][1]) : "l"(ea.x), "l"(vy));
                asm("fma.rn.f32x2 %0, %1, %2, %0;" : "+l"(acc2[1][0]) : "l"(ea.y), "l"(vx));
                asm("fma.rn.f32x2 %0, %1, %2, %0;" : "+l"(acc2[1][1]) : "l"(ea.y), "l"(vy));
                asm("fma.rn.f32x2 %0, %1, %2, %0;" : "+l"(acc2[2][0]) : "l"(eb.x), "l"(vx));
                asm("fma.rn.f32x2 %0, %1, %2, %0;" : "+l"(acc2[2][1]) : "l"(eb.x), "l"(vy));
                asm("fma.rn.f32x2 %0, %1, %2, %0;" : "+l"(acc2[3][0]) : "l"(eb.y), "l"(vx));
                asm("fma.rn.f32x2 %0, %1, %2, %0;" : "+l"(acc2[3][1]) : "l"(eb.y), "l"(vy));
            }
#pragma unroll
            for (int p = 0; p < 4; p++) {
                float l0, h0, l1, h1;
                asm("mov.b64 {%0, %1}, %2;" : "=f"(l0), "=f"(h0) : "l"(acc2[p][0]));
                asm("mov.b64 {%0, %1}, %2;" : "=f"(l1), "=f"(h1) : "l"(acc2[p][1]));
                *(float2*)&g_pAV[qt][s][2 * p][c]     = make_float2(l0, l1);
                *(float2*)&g_pAV[qt][s][2 * p + 1][c] = make_float2(h0, h1);
            }
        }
    }

    // ---- Ticket: last split CTA for this qtile performs the reduction ----
    __syncthreads();
    if (tid == 0) {
        __threadfence();                               // release scratch writes
        unsigned o = atomicAdd(&g_tick[qt], 1u);
        s_last = (o == SPL - 1u) ? 1 : 0;
    }
    __syncthreads();
    if (!s_last) return;
    __threadfence();                                   // acquire peers' scratch

    const int nact = uniform ? SPL : ((vl + TJS - 1) / TJS);   // active splits
    if (tid < QT) {
        float t = 0.f;
        for (int ss = 0; ss < nact; ss++) t += g_psum[qt][ss][tid];
        s_inv[tid] = 1.f / t;
    }
    __syncthreads();

    for (int i = tid; i < QT * (DV_ / 4); i += NTH) {
        const int q = i >> 7, c = (i & 127) * 4;
        float4 a = make_float4(0.f, 0.f, 0.f, 0.f);
        for (int ss = 0; ss < nact; ss++) {
            float4 p = *(const float4*)&g_pAV[qt][ss][q][c];
            a.x += p.x; a.y += p.y; a.z += p.z; a.w += p.w;
        }
        const float inv = s_inv[q];
        *(float4*)&out[(size_t)(b * LQ_ + q0 + q) * DV_ + c] =
            make_float4(a.x * inv, a.y * inv, a.z * inv, a.w * inv);
    }
}

extern "C" void kernel_launch(void* const* d_in, const int* in_sizes, int n_in,
                              void* d_out, int out_size) {
    const float* queries = (const float*)d_in[0];
    const float* keys    = (const float*)d_in[1];
    const float* values  = (const float*)d_in[2];
    const float* Wq      = (const float*)d_in[3];
    const float* Wk      = (const float*)d_in[4];
    const float* wv      = (const float*)d_in[5];
    const int*   vlen    = (const int*)d_in[6];
    float* out = (float*)d_out;

    to_half<<<1024, 256>>>(queries, keys, Wq, Wk);
    proj_mma<<<dim3(H_ / 64, 16 + 128), 128>>>();
    partial_attn<<<NQT * SPL, NTH>>>(values, wv, vlen, out);
}